// round 15
// baseline (speedup 1.0000x reference)
#include <cuda_runtime.h>
#include <math.h>
#include <stdint.h>

// Verified: U_re/U_im 4718592 = 4*131072*9, W_re/W_im 9437184 = 8*131072*9,
// wgt 32 = 4*8. out: 4718592 float32 = REAL PART of exp(E) @ U.
#define REF_NSITE (32*16*16*16)
#define REF_NMU   4
#define REF_NFEAT 8
#define NWARP 4
#define NBUF  3                   // pipeline depth (ring buffers per warp)
#define TFLOATS 576               // one tile: 288 re + 288 im floats

__device__ __forceinline__ void cp16(uint32_t saddr, const void* gaddr) {
    asm volatile("cp.async.cg.shared.global [%0], [%1], 16;\n"
                 :: "r"(saddr), "l"(gaddr));
}
__device__ __forceinline__ void cp_commit() {
    asm volatile("cp.async.commit_group;\n");
}
template<int N>
__device__ __forceinline__ void cp_wait() {
    asm volatile("cp.async.wait_group %0;\n" :: "n"(N));
}

// From Q components (hermitian traceless: q2 = -q0-q1) and U, compute
// rr = Re( exp(iQ) @ U ) via Morningstar-Peardon closed form.
__device__ __forceinline__ void epilogue_from_q(
    float q0, float q1,
    float q01r, float q01i, float q02r, float q02i, float q12r, float q12i,
    const float Urm[9], const float Uim[9], float rr[9])
{
    float q2 = -q0 - q1;

    float n01 = q01r*q01r + q01i*q01i;
    float n02 = q02r*q02r + q02i*q02i;
    float n12 = q12r*q12r + q12i*q12i;

    float c1 = 0.5f*(q0*q0 + q1*q1 + q2*q2) + n01 + n02 + n12;
    float pr = q01r*q12r - q01i*q12i;
    float pi = q01r*q12i + q01i*q12r;
    float c0 = q0*q1*q2 - q0*n12 - q1*n02 - q2*n01
             + 2.f*(pr*q02r + pi*q02i);

    float f0r, f0i, f1r, f1i, f2r, f2i;
    if (c1 < 1e-9f) {
        f0r = 1.f; f0i = 0.f; f1r = 0.f; f1i = 1.f; f2r = -0.5f; f2i = 0.f;
    } else {
        bool neg = (c0 < 0.f);
        float c0a   = fabsf(c0);
        float sq3   = sqrtf(c1 * (1.f/3.f));
        float c0max = 2.f * (c1 * (1.f/3.f)) * sq3;
        float r     = fminf(c0a / c0max, 1.f);
        float th3   = acosf(r) * (1.f/3.f);
        float s3, c3; sincosf(th3, &s3, &c3);
        float u = sq3 * c3;
        float w = (sq3 * 1.7320508075688772f) * s3;
        float u2 = u*u, w2 = w*w;

        float sw, cw; sincosf(w, &sw, &cw);
        float xi0 = (fabsf(w) > 0.05f) ? (sw / w)
                  : (1.f - w2*(1.f/6.f)*(1.f - w2*0.05f));
        float su, cu; sincosf(u, &su, &cu);
        float s2u = 2.f*su*cu;
        float c2u = 1.f - 2.f*su*su;

        float dinv = 1.f / (9.f*u2 - w2);

        float T0r = 8.f*u2*cw;
        float T0i = 2.f*u*(3.f*u2 + w2)*xi0;
        float h0r = (u2 - w2)*c2u + cu*T0r + su*T0i;
        float h0i = (u2 - w2)*s2u + cu*T0i - su*T0r;
        float T1r = 2.f*u*cw;
        float T1i = -(3.f*u2 - w2)*xi0;
        float h1r = 2.f*u*c2u - (cu*T1r + su*T1i);
        float h1i = 2.f*u*s2u - (cu*T1i - su*T1r);
        float T2i = 3.f*u*xi0;
        float h2r = c2u - (cu*cw + su*T2i);
        float h2i = s2u - (cu*T2i - su*cw);

        f0r = h0r*dinv; f0i = h0i*dinv;
        f1r = h1r*dinv; f1i = h1i*dinv;
        f2r = h2r*dinv; f2i = h2i*dinv;
        if (neg) { f0i = -f0i; f1r = -f1r; f2i = -f2i; }
    }

    float s01 = q0 + q1, s02 = q0 + q2, s12 = q1 + q2;
    float Q200 = q0*q0 + n01 + n02;
    float Q211 = q1*q1 + n01 + n12;
    float Q222 = q2*q2 + n02 + n12;
    float Q201r = q01r*s01 + (q02r*q12r + q02i*q12i);
    float Q201i = q01i*s01 + (q02i*q12r - q02r*q12i);
    float Q202r = q02r*s02 + (q01r*q12r - q01i*q12i);
    float Q202i = q02i*s02 + (q01r*q12i + q01i*q12r);
    float Q212r = q12r*s12 + (q01r*q02r + q01i*q02i);
    float Q212i = q12i*s12 + (q01r*q02i - q01i*q02r);

    float Gr[9], Gi[9];
    Gr[0] = f0r + f1r*q0 + f2r*Q200;  Gi[0] = f0i + f1i*q0 + f2i*Q200;
    Gr[4] = f0r + f1r*q1 + f2r*Q211;  Gi[4] = f0i + f1i*q1 + f2i*Q211;
    Gr[8] = f0r + f1r*q2 + f2r*Q222;  Gi[8] = f0i + f1i*q2 + f2i*Q222;
    Gr[1] = (f1r*q01r - f1i*q01i) + (f2r*Q201r - f2i*Q201i);
    Gi[1] = (f1r*q01i + f1i*q01r) + (f2r*Q201i + f2i*Q201r);
    Gr[3] = (f1r*q01r + f1i*q01i) + (f2r*Q201r + f2i*Q201i);
    Gi[3] = (f1i*q01r - f1r*q01i) + (f2i*Q201r - f2r*Q201i);
    Gr[2] = (f1r*q02r - f1i*q02i) + (f2r*Q202r - f2i*Q202i);
    Gi[2] = (f1r*q02i + f1i*q02r) + (f2r*Q202i + f2i*Q202r);
    Gr[6] = (f1r*q02r + f1i*q02i) + (f2r*Q202r + f2i*Q202i);
    Gi[6] = (f1i*q02r - f1r*q02i) + (f2i*Q202r - f2r*Q202i);
    Gr[5] = (f1r*q12r - f1i*q12i) + (f2r*Q212r - f2i*Q212i);
    Gi[5] = (f1r*q12i + f1i*q12r) + (f2r*Q212i + f2i*Q212r);
    Gr[7] = (f1r*q12r + f1i*q12i) + (f2r*Q212r + f2i*Q212i);
    Gi[7] = (f1i*q12r - f1r*q12i) + (f2i*Q212r - f2r*Q212i);

#pragma unroll
    for (int a = 0; a < 3; ++a)
#pragma unroll
        for (int b = 0; b < 3; ++b) {
            float acc = 0.f;
#pragma unroll
            for (int c = 0; c < 3; ++c) {
                acc = fmaf(Gr[a*3+c], Urm[c*3+b], acc);
                acc = fmaf(-Gi[a*3+c], Uim[c*3+b], acc);
            }
            rr[a*3+b] = acc;
        }
}

// Per-warp cp.async pipeline: 12 tiles (8 W + 4 U) streamed through a 3-deep
// smem ring. Loads stay in flight during every compute phase -> sustained MLP.
template<int NMU>
__global__ void __launch_bounds__(32*NWARP, 6)
lge_exp_kernel(const float* __restrict__ U_re,
               const float* __restrict__ U_im,
               const float* __restrict__ W_re,
               const float* __restrict__ W_im,
               const float* __restrict__ wgt,
               float* __restrict__ out,
               int nsite, int nfeat,
               long cW, long cU, long cWg, long o_cap)
{
    __shared__ float sbuf[NWARP][NBUF][TFLOATS];   // 27648 B
    __shared__ float rbuf[NWARP][288];             //  4608 B

    const int w    = threadIdx.x >> 5;
    const int lane = threadIdx.x & 31;
    const long ws  = (long)blockIdx.x * (32*NWARP) + w*32;
    const long s   = ws + lane;

    bool fast = (ws + 32 <= nsite) && ((nsite & 3) == 0);
    if (fast) {
        long wmax = ((long)(nfeat - 1) * nsite + ws) * 9 + 288;
        long umax = ((long)(NMU  - 1) * nsite + ws) * 9 + 288;
        fast = (wmax <= cW) && (umax <= cU) && (umax <= o_cap)
            && (((long)NMU * nfeat) <= cWg);
    }

    float A[NMU][8];
#pragma unroll
    for (int u = 0; u < NMU; ++u)
#pragma unroll
        for (int k = 0; k < 8; ++k) A[u][k] = 0.f;

    if (fast) {
        const int T = nfeat + NMU;                 // total tiles per warp
        const uint32_t sb0 = (uint32_t)__cvta_generic_to_shared(&sbuf[w][0][0]);

        // issue one tile's loads (288 re + 288 im floats = 72+72 16B chunks)
        auto issue = [&](int t, int b) {
            long g; const float *rp, *ip;
            if (t < nfeat) { g = ((long)t*nsite + ws)*9; rp = W_re+g; ip = W_im+g; }
            else { g = ((long)(t-nfeat)*nsite + ws)*9; rp = U_re+g; ip = U_im+g; }
            uint32_t sre = sb0 + (uint32_t)b * (TFLOATS*4);
            uint32_t sim = sre + 288*4;
            cp16(sre + lane*16,        rp + lane*4);
            cp16(sre + (lane+32)*16,   rp + (lane+32)*4);
            if (lane < 8) cp16(sre + (lane+64)*16, rp + (lane+64)*4);
            cp16(sim + lane*16,        ip + lane*4);
            cp16(sim + (lane+32)*16,   ip + (lane+32)*4);
            if (lane < 8) cp16(sim + (lane+64)*16, ip + (lane+64)*4);
        };

        // prologue: fill the ring
        for (int t = 0; t < NBUF && t < T; ++t) { issue(t, t % NBUF); cp_commit(); }

        const int b0 = lane * 9;
        for (int t = 0; t < T; ++t) {
            int rem = T - 1 - t;                   // groups that may stay pending
            if (rem >= NBUF-1) cp_wait<NBUF-1>();
            else if (rem == 1) cp_wait<1>();
            else               cp_wait<0>();
            __syncwarp();

            const float* tre = &sbuf[w][t % NBUF][0];
            const float* tim = tre + 288;

            if (t < nfeat) {
                float mr[9], mi[9];
#pragma unroll
                for (int e = 0; e < 9; ++e) { mr[e] = tre[b0+e]; mi[e] = tim[b0+e]; }
                __syncwarp();                       // tile consumed; buffer reusable
                if (t + NBUF < T) { issue(t + NBUF, t % NBUF); cp_commit(); }

                float tau3 = (mi[0] + mi[4] + mi[8]) * (2.f/3.f);
                float p0   = 2.f*mi[0] - tau3;
                float p1   = 2.f*mi[4] - tau3;
                float p01r = mi[1] + mi[3], p01i = mr[3] - mr[1];
                float p02r = mi[2] + mi[6], p02i = mr[6] - mr[2];
                float p12r = mi[5] + mi[7], p12i = mr[7] - mr[5];
#pragma unroll
                for (int u = 0; u < NMU; ++u) {
                    float wu = __ldg(&wgt[(long)u * nfeat + t]);
                    A[u][0] = fmaf(wu, p0,   A[u][0]);
                    A[u][1] = fmaf(wu, p1,   A[u][1]);
                    A[u][2] = fmaf(wu, p01r, A[u][2]);
                    A[u][3] = fmaf(wu, p01i, A[u][3]);
                    A[u][4] = fmaf(wu, p02r, A[u][4]);
                    A[u][5] = fmaf(wu, p02i, A[u][5]);
                    A[u][6] = fmaf(wu, p12r, A[u][6]);
                    A[u][7] = fmaf(wu, p12i, A[u][7]);
                }
            } else {
                int mu = t - nfeat;
                float Urm[9], Uim[9];
#pragma unroll
                for (int e = 0; e < 9; ++e) { Urm[e] = tre[b0+e]; Uim[e] = tim[b0+e]; }
                __syncwarp();
                if (t + NBUF < T) { issue(t + NBUF, t % NBUF); cp_commit(); }

                float rr[9];
                epilogue_from_q(A[mu][0], A[mu][1], A[mu][2], A[mu][3],
                                A[mu][4], A[mu][5], A[mu][6], A[mu][7],
                                Urm, Uim, rr);
#pragma unroll
                for (int e = 0; e < 9; ++e) rbuf[w][b0 + e] = rr[e];
                __syncwarp();
                long g = ((long)mu * nsite + ws) * 9;
#pragma unroll
                for (int k = 0; k < 9; ++k)
                    out[g + lane + 32*k] = rbuf[w][lane + 32*k];
                // loop-top syncwarp orders these reads vs next iteration's writes
            }
        }
        return;
    }

    // ---- guarded scalar fallback (partial warp-tiles / odd geometry) ----
    if (s >= nsite) return;
    for (int i = 0; i < nfeat; ++i) {
        float wv[NMU];
#pragma unroll
        for (int u = 0; u < NMU; ++u) {
            long widx = (long)u * nfeat + i;
            wv[u] = (widx < cWg) ? __ldg(&wgt[widx]) : 0.f;
        }
        long base = ((long)i * nsite + s) * 9;
        if (base + 9 > cW) continue;
        float mr[9], mi[9];
#pragma unroll
        for (int e = 0; e < 9; ++e) {
            mr[e] = __ldg(W_re + base + e);
            mi[e] = __ldg(W_im + base + e);
        }
        float tau3 = (mi[0] + mi[4] + mi[8]) * (2.f/3.f);
        float p0   = 2.f*mi[0] - tau3;
        float p1   = 2.f*mi[4] - tau3;
        float p01r = mi[1] + mi[3], p01i = mr[3] - mr[1];
        float p02r = mi[2] + mi[6], p02i = mr[6] - mr[2];
        float p12r = mi[5] + mi[7], p12i = mr[7] - mr[5];
#pragma unroll
        for (int u = 0; u < NMU; ++u) {
            float wu = wv[u];
            A[u][0] = fmaf(wu, p0,   A[u][0]);
            A[u][1] = fmaf(wu, p1,   A[u][1]);
            A[u][2] = fmaf(wu, p01r, A[u][2]);
            A[u][3] = fmaf(wu, p01i, A[u][3]);
            A[u][4] = fmaf(wu, p02r, A[u][4]);
            A[u][5] = fmaf(wu, p02i, A[u][5]);
            A[u][6] = fmaf(wu, p12r, A[u][6]);
            A[u][7] = fmaf(wu, p12i, A[u][7]);
        }
    }
#pragma unroll
    for (int mu = 0; mu < NMU; ++mu) {
        long off = ((long)mu * nsite + s) * 9;
        bool ld_ok = (off + 9 <= cU);
        float Urm[9], Uim[9];
#pragma unroll
        for (int e = 0; e < 9; ++e) {
            Urm[e] = ld_ok ? __ldg(U_re + off + e) : 0.f;
            Uim[e] = ld_ok ? __ldg(U_im + off + e) : 0.f;
        }
        float rr[9];
        epilogue_from_q(A[mu][0], A[mu][1], A[mu][2], A[mu][3],
                        A[mu][4], A[mu][5], A[mu][6], A[mu][7],
                        Urm, Uim, rr);
#pragma unroll
        for (int e = 0; e < 9; ++e) {
            long idx = off + e;
            if (idx < o_cap) out[idx] = rr[e];
        }
    }
}

extern "C" void kernel_launch(void* const* d_in, const int* in_sizes, int n_in,
                              void* d_out, int out_size)
{
    // weights = smallest input
    int wi_idx = 0;
    for (int i = 1; i < n_in; ++i)
        if (in_sizes[i] < in_sizes[wi_idx]) wi_idx = i;
    const float* wgt = (const float*)d_in[wi_idx];
    long wgt_n = in_sizes[wi_idx];

    const float* mat[4]; long msz[4]; int nm = 0;
    for (int i = 0; i < n_in && nm < 4; ++i)
        if (i != wi_idx) { mat[nm] = (const float*)d_in[i]; msz[nm] = in_sizes[i]; ++nm; }

    const float *Ur=0,*Ui=0,*Wr=0,*Wi=0;
    long sU=0, sW=0, nsite=0;
    int nmu=0, nfeat=0;
    bool ok = (nm == 4 && n_in == 5 && wgt_n >= 1);

    if (ok) {
        int p0b = -1;
        for (int j = 1; j < 4; ++j) if (msz[j] == msz[0]) { p0b = j; break; }
        int p1a = -1, p1b = -1;
        if (p0b > 0)
            for (int j = 1; j < 4; ++j) if (j != p0b) { if (p1a < 0) p1a = j; else p1b = j; }
        ok = (p0b > 0 && p1a > 0 && p1b > 0 && msz[p1a] == msz[p1b]);

        if (ok) {
            long sA = msz[0], sB = msz[p1a];
            bool firstIsU;
            if (sA == sB) firstIsU = true;
            else {
                bool aU = (sA == (long)out_size) || (2*sA == (long)out_size);
                bool bU = (sB == (long)out_size) || (2*sB == (long)out_size);
                firstIsU = aU || !bU;
            }
            if (firstIsU) { Ur=mat[0]; Ui=mat[p0b]; Wr=mat[p1a]; Wi=mat[p1b]; sU=sA; sW=sB; }
            else          { Wr=mat[0]; Wi=mat[p0b]; Ur=mat[p1a]; Ui=mat[p1b]; sU=sB; sW=sA; }

            double nmud = sqrt((double)wgt_n * (double)sU / (double)sW);
            nmu = (int)(nmud + 0.5);
            ok = (nmu >= 1 && nmu <= 4 && wgt_n % nmu == 0);
            if (ok) {
                nfeat = (int)(wgt_n / nmu);
                ok = (sU % (9L * nmu) == 0);
                if (ok) {
                    nsite = sU / (9L * nmu);
                    ok = (nsite > 0) && (sW == 9L * (long)nfeat * nsite);
                }
            }
        }
    }

    long cU, cW, cWg;
    if (ok) { cU = sU; cW = sW; cWg = wgt_n; }
    else {
        if (n_in < 5) return;
        Ur = (const float*)d_in[0]; Ui = (const float*)d_in[1];
        Wr = (const float*)d_in[2]; Wi = (const float*)d_in[3];
        wgt = (const float*)d_in[4];
        long c0 = in_sizes[0], c1 = in_sizes[1];
        long c2 = in_sizes[2], c3 = in_sizes[3];
        cU = (c0 < c1) ? c0 : c1;
        cW = (c2 < c3) ? c2 : c3;
        cWg = in_sizes[4];
        nmu = REF_NMU; nfeat = REF_NFEAT; nsite = REF_NSITE;
    }

    float* out = (float*)d_out;
    long o_cap = (long)out_size;     // float element capacity (real part only)

    const int tpb = 32*NWARP;
    dim3 block(tpb);
    dim3 grid((unsigned)((nsite + tpb - 1) / tpb));

    switch (nmu) {
    case 1: lge_exp_kernel<1><<<grid, block>>>(Ur,Ui,Wr,Wi,wgt,out,(int)nsite,nfeat,cW,cU,cWg,o_cap); break;
    case 2: lge_exp_kernel<2><<<grid, block>>>(Ur,Ui,Wr,Wi,wgt,out,(int)nsite,nfeat,cW,cU,cWg,o_cap); break;
    case 3: lge_exp_kernel<3><<<grid, block>>>(Ur,Ui,Wr,Wi,wgt,out,(int)nsite,nfeat,cW,cU,cWg,o_cap); break;
    default: lge_exp_kernel<4><<<grid, block>>>(Ur,Ui,Wr,Wi,wgt,out,(int)nsite,nfeat,cW,cU,cWg,o_cap); break;
    }
}

// round 16
// speedup vs baseline: 1.5785x; 1.5785x over previous
#include <cuda_runtime.h>
#include <math.h>

// Verified: U_re/U_im 4718592 = 4*131072*9, W_re/W_im 9437184 = 8*131072*9,
// wgt 32 = 4*8. out: 4718592 float32 = REAL PART of exp(E) @ U.
#define REF_NSITE (32*16*16*16)
#define REF_NMU   4
#define REF_NFEAT 8

// From Q components (hermitian traceless: q2 = -q0-q1) and U, compute
// rr = Re( exp(iQ) @ U ) via Morningstar-Peardon closed form.
__device__ __forceinline__ void epilogue_from_q(
    float q0, float q1,
    float q01r, float q01i, float q02r, float q02i, float q12r, float q12i,
    const float Urm[9], const float Uim[9], float rr[9])
{
    float q2 = -q0 - q1;

    float n01 = q01r*q01r + q01i*q01i;
    float n02 = q02r*q02r + q02i*q02i;
    float n12 = q12r*q12r + q12i*q12i;

    float c1 = 0.5f*(q0*q0 + q1*q1 + q2*q2) + n01 + n02 + n12;
    float pr = q01r*q12r - q01i*q12i;
    float pi = q01r*q12i + q01i*q12r;
    float c0 = q0*q1*q2 - q0*n12 - q1*n02 - q2*n01
             + 2.f*(pr*q02r + pi*q02i);

    float f0r, f0i, f1r, f1i, f2r, f2i;
    if (c1 < 1e-9f) {
        f0r = 1.f; f0i = 0.f; f1r = 0.f; f1i = 1.f; f2r = -0.5f; f2i = 0.f;
    } else {
        bool neg = (c0 < 0.f);
        float c0a   = fabsf(c0);
        float sq3   = sqrtf(c1 * (1.f/3.f));
        float c0max = 2.f * (c1 * (1.f/3.f)) * sq3;
        float r     = fminf(c0a / c0max, 1.f);
        float th3   = acosf(r) * (1.f/3.f);
        float s3, c3; sincosf(th3, &s3, &c3);
        float u = sq3 * c3;
        float w = (sq3 * 1.7320508075688772f) * s3;
        float u2 = u*u, w2 = w*w;

        float sw, cw; sincosf(w, &sw, &cw);
        float xi0 = (fabsf(w) > 0.05f) ? (sw / w)
                  : (1.f - w2*(1.f/6.f)*(1.f - w2*0.05f));
        float su, cu; sincosf(u, &su, &cu);
        float s2u = 2.f*su*cu;
        float c2u = 1.f - 2.f*su*su;

        float dinv = 1.f / (9.f*u2 - w2);

        float T0r = 8.f*u2*cw;
        float T0i = 2.f*u*(3.f*u2 + w2)*xi0;
        float h0r = (u2 - w2)*c2u + cu*T0r + su*T0i;
        float h0i = (u2 - w2)*s2u + cu*T0i - su*T0r;
        float T1r = 2.f*u*cw;
        float T1i = -(3.f*u2 - w2)*xi0;
        float h1r = 2.f*u*c2u - (cu*T1r + su*T1i);
        float h1i = 2.f*u*s2u - (cu*T1i - su*T1r);
        float T2i = 3.f*u*xi0;
        float h2r = c2u - (cu*cw + su*T2i);
        float h2i = s2u - (cu*T2i - su*cw);

        f0r = h0r*dinv; f0i = h0i*dinv;
        f1r = h1r*dinv; f1i = h1i*dinv;
        f2r = h2r*dinv; f2i = h2i*dinv;
        if (neg) { f0i = -f0i; f1r = -f1r; f2i = -f2i; }
    }

    float s01 = q0 + q1, s02 = q0 + q2, s12 = q1 + q2;
    float Q200 = q0*q0 + n01 + n02;
    float Q211 = q1*q1 + n01 + n12;
    float Q222 = q2*q2 + n02 + n12;
    float Q201r = q01r*s01 + (q02r*q12r + q02i*q12i);
    float Q201i = q01i*s01 + (q02i*q12r - q02r*q12i);
    float Q202r = q02r*s02 + (q01r*q12r - q01i*q12i);
    float Q202i = q02i*s02 + (q01r*q12i + q01i*q12r);
    float Q212r = q12r*s12 + (q01r*q02r + q01i*q02i);
    float Q212i = q12i*s12 + (q01r*q02i - q01i*q02r);

    float Gr[9], Gi[9];
    Gr[0] = f0r + f1r*q0 + f2r*Q200;  Gi[0] = f0i + f1i*q0 + f2i*Q200;
    Gr[4] = f0r + f1r*q1 + f2r*Q211;  Gi[4] = f0i + f1i*q1 + f2i*Q211;
    Gr[8] = f0r + f1r*q2 + f2r*Q222;  Gi[8] = f0i + f1i*q2 + f2i*Q222;
    Gr[1] = (f1r*q01r - f1i*q01i) + (f2r*Q201r - f2i*Q201i);
    Gi[1] = (f1r*q01i + f1i*q01r) + (f2r*Q201i + f2i*Q201r);
    Gr[3] = (f1r*q01r + f1i*q01i) + (f2r*Q201r + f2i*Q201i);
    Gi[3] = (f1i*q01r - f1r*q01i) + (f2i*Q201r - f2r*Q201i);
    Gr[2] = (f1r*q02r - f1i*q02i) + (f2r*Q202r - f2i*Q202i);
    Gi[2] = (f1r*q02i + f1i*q02r) + (f2r*Q202i + f2i*Q202r);
    Gr[6] = (f1r*q02r + f1i*q02i) + (f2r*Q202r + f2i*Q202i);
    Gi[6] = (f1i*q02r - f1r*q02i) + (f2i*Q202r - f2r*Q202i);
    Gr[5] = (f1r*q12r - f1i*q12i) + (f2r*Q212r - f2i*Q212i);
    Gi[5] = (f1r*q12i + f1i*q12r) + (f2r*Q212i + f2i*Q212r);
    Gr[7] = (f1r*q12r + f1i*q12i) + (f2r*Q212r + f2i*Q212i);
    Gi[7] = (f1i*q12r - f1r*q12i) + (f2i*Q212r - f2r*Q212i);

#pragma unroll
    for (int a = 0; a < 3; ++a)
#pragma unroll
        for (int b = 0; b < 3; ++b) {
            float acc = 0.f;
#pragma unroll
            for (int c = 0; c < 3; ++c) {
                acc = fmaf(Gr[a*3+c], Urm[c*3+b], acc);
                acc = fmaf(-Gi[a*3+c], Uim[c*3+b], acc);
            }
            rr[a*3+b] = acc;
        }
}

// FAST PATH: geometry fully compile-time. Both loops unrolled so ptxas can
// front-batch loads across iterations (the runtime-trip loops in prior rounds
// blocked this). All addressing 32-bit (max index < 2^31, host-verified).
template<int NMU, int NFEAT>
__global__ void __launch_bounds__(128, 4)
lge_fast(const float* __restrict__ U_re,
         const float* __restrict__ U_im,
         const float* __restrict__ W_re,
         const float* __restrict__ W_im,
         const float* __restrict__ wgt,
         float* __restrict__ out,
         int nsite)
{
    int s = blockIdx.x * 128 + threadIdx.x;
    if (s >= nsite) return;
    const int N9 = nsite * 9;
    const int b  = s * 9;

    float A[NMU][8];
#pragma unroll
    for (int u = 0; u < NMU; ++u)
#pragma unroll
        for (int k = 0; k < 8; ++k) A[u][k] = 0.f;

#pragma unroll
    for (int i = 0; i < NFEAT; ++i) {
        const float* wr = W_re + i * N9 + b;
        const float* wi = W_im + i * N9 + b;
        float mr[9], mi[9];
#pragma unroll
        for (int e = 0; e < 9; ++e) { mr[e] = __ldg(wr + e); mi[e] = __ldg(wi + e); }

        float tau3 = (mi[0] + mi[4] + mi[8]) * (2.f/3.f);
        float p0   = 2.f*mi[0] - tau3;
        float p1   = 2.f*mi[4] - tau3;
        float p01r = mi[1] + mi[3], p01i = mr[3] - mr[1];
        float p02r = mi[2] + mi[6], p02i = mr[6] - mr[2];
        float p12r = mi[5] + mi[7], p12i = mr[7] - mr[5];

#pragma unroll
        for (int u = 0; u < NMU; ++u) {
            float wu = __ldg(&wgt[u * NFEAT + i]);
            A[u][0] = fmaf(wu, p0,   A[u][0]);
            A[u][1] = fmaf(wu, p1,   A[u][1]);
            A[u][2] = fmaf(wu, p01r, A[u][2]);
            A[u][3] = fmaf(wu, p01i, A[u][3]);
            A[u][4] = fmaf(wu, p02r, A[u][4]);
            A[u][5] = fmaf(wu, p02i, A[u][5]);
            A[u][6] = fmaf(wu, p12r, A[u][6]);
            A[u][7] = fmaf(wu, p12i, A[u][7]);
        }
    }

#pragma unroll
    for (int mu = 0; mu < NMU; ++mu) {
        const int off = mu * N9 + b;
        float Urm[9], Uim[9];
#pragma unroll
        for (int e = 0; e < 9; ++e) {
            Urm[e] = __ldg(U_re + off + e);
            Uim[e] = __ldg(U_im + off + e);
        }
        float rr[9];
        epilogue_from_q(A[mu][0], A[mu][1], A[mu][2], A[mu][3],
                        A[mu][4], A[mu][5], A[mu][6], A[mu][7],
                        Urm, Uim, rr);
#pragma unroll
        for (int e = 0; e < 9; ++e) out[off + e] = rr[e];
    }
}

// Generic guarded fallback (any geometry; cannot fault).
template<int NMU>
__global__ void __launch_bounds__(128, 6)
lge_generic(const float* __restrict__ U_re,
            const float* __restrict__ U_im,
            const float* __restrict__ W_re,
            const float* __restrict__ W_im,
            const float* __restrict__ wgt,
            float* __restrict__ out,
            int nsite, int nfeat,
            long cW, long cU, long cWg, long o_cap)
{
    int s = blockIdx.x * blockDim.x + threadIdx.x;
    if (s >= nsite) return;

    float A[NMU][8];
#pragma unroll
    for (int u = 0; u < NMU; ++u)
#pragma unroll
        for (int k = 0; k < 8; ++k) A[u][k] = 0.f;

    for (int i = 0; i < nfeat; ++i) {
        float wv[NMU];
#pragma unroll
        for (int u = 0; u < NMU; ++u) {
            long widx = (long)u * nfeat + i;
            wv[u] = (widx < cWg) ? __ldg(&wgt[widx]) : 0.f;
        }
        long base = ((long)i * nsite + s) * 9;
        if (base + 9 > cW) continue;
        float mr[9], mi[9];
#pragma unroll
        for (int e = 0; e < 9; ++e) {
            mr[e] = __ldg(W_re + base + e);
            mi[e] = __ldg(W_im + base + e);
        }
        float tau3 = (mi[0] + mi[4] + mi[8]) * (2.f/3.f);
        float p0   = 2.f*mi[0] - tau3;
        float p1   = 2.f*mi[4] - tau3;
        float p01r = mi[1] + mi[3], p01i = mr[3] - mr[1];
        float p02r = mi[2] + mi[6], p02i = mr[6] - mr[2];
        float p12r = mi[5] + mi[7], p12i = mr[7] - mr[5];
#pragma unroll
        for (int u = 0; u < NMU; ++u) {
            float wu = wv[u];
            A[u][0] = fmaf(wu, p0,   A[u][0]);
            A[u][1] = fmaf(wu, p1,   A[u][1]);
            A[u][2] = fmaf(wu, p01r, A[u][2]);
            A[u][3] = fmaf(wu, p01i, A[u][3]);
            A[u][4] = fmaf(wu, p02r, A[u][4]);
            A[u][5] = fmaf(wu, p02i, A[u][5]);
            A[u][6] = fmaf(wu, p12r, A[u][6]);
            A[u][7] = fmaf(wu, p12i, A[u][7]);
        }
    }
#pragma unroll
    for (int mu = 0; mu < NMU; ++mu) {
        long off = ((long)mu * nsite + s) * 9;
        bool ld_ok = (off + 9 <= cU);
        float Urm[9], Uim[9];
#pragma unroll
        for (int e = 0; e < 9; ++e) {
            Urm[e] = ld_ok ? __ldg(U_re + off + e) : 0.f;
            Uim[e] = ld_ok ? __ldg(U_im + off + e) : 0.f;
        }
        float rr[9];
        epilogue_from_q(A[mu][0], A[mu][1], A[mu][2], A[mu][3],
                        A[mu][4], A[mu][5], A[mu][6], A[mu][7],
                        Urm, Uim, rr);
#pragma unroll
        for (int e = 0; e < 9; ++e) {
            long idx = off + e;
            if (idx < o_cap) out[idx] = rr[e];
        }
    }
}

extern "C" void kernel_launch(void* const* d_in, const int* in_sizes, int n_in,
                              void* d_out, int out_size)
{
    // weights = smallest input
    int wi_idx = 0;
    for (int i = 1; i < n_in; ++i)
        if (in_sizes[i] < in_sizes[wi_idx]) wi_idx = i;
    const float* wgt = (const float*)d_in[wi_idx];
    long wgt_n = in_sizes[wi_idx];

    const float* mat[4]; long msz[4]; int nm = 0;
    for (int i = 0; i < n_in && nm < 4; ++i)
        if (i != wi_idx) { mat[nm] = (const float*)d_in[i]; msz[nm] = in_sizes[i]; ++nm; }

    const float *Ur=0,*Ui=0,*Wr=0,*Wi=0;
    long sU=0, sW=0, nsite=0;
    int nmu=0, nfeat=0;
    bool ok = (nm == 4 && n_in == 5 && wgt_n >= 1);

    if (ok) {
        int p0b = -1;
        for (int j = 1; j < 4; ++j) if (msz[j] == msz[0]) { p0b = j; break; }
        int p1a = -1, p1b = -1;
        if (p0b > 0)
            for (int j = 1; j < 4; ++j) if (j != p0b) { if (p1a < 0) p1a = j; else p1b = j; }
        ok = (p0b > 0 && p1a > 0 && p1b > 0 && msz[p1a] == msz[p1b]);

        if (ok) {
            long sA = msz[0], sB = msz[p1a];
            bool firstIsU;
            if (sA == sB) firstIsU = true;
            else {
                bool aU = (sA == (long)out_size) || (2*sA == (long)out_size);
                bool bU = (sB == (long)out_size) || (2*sB == (long)out_size);
                firstIsU = aU || !bU;
            }
            if (firstIsU) { Ur=mat[0]; Ui=mat[p0b]; Wr=mat[p1a]; Wi=mat[p1b]; sU=sA; sW=sB; }
            else          { Wr=mat[0]; Wi=mat[p0b]; Ur=mat[p1a]; Ui=mat[p1b]; sU=sB; sW=sA; }

            double nmud = sqrt((double)wgt_n * (double)sU / (double)sW);
            nmu = (int)(nmud + 0.5);
            ok = (nmu >= 1 && nmu <= 4 && wgt_n % nmu == 0);
            if (ok) {
                nfeat = (int)(wgt_n / nmu);
                ok = (sU % (9L * nmu) == 0);
                if (ok) {
                    nsite = sU / (9L * nmu);
                    ok = (nsite > 0) && (sW == 9L * (long)nfeat * nsite);
                }
            }
        }
    }

    float* out = (float*)d_out;
    long o_cap = (long)out_size;     // float element capacity (real part only)

    // FAST dispatch: exact verified geometry, offsets fit in int32, output
    // capacity covers the full U-shaped result.
    if (ok && nmu == 4 && nfeat == 8 &&
        sW < 0x7FFFFF00L && sU < 0x7FFFFF00L && o_cap >= sU) {
        dim3 block(128);
        dim3 grid((unsigned)((nsite + 127) / 128));
        lge_fast<4, 8><<<grid, block>>>(Ur, Ui, Wr, Wi, wgt, out, (int)nsite);
        return;
    }

    long cU, cW, cWg;
    if (ok) { cU = sU; cW = sW; cWg = wgt_n; }
    else {
        if (n_in < 5) return;
        Ur = (const float*)d_in[0]; Ui = (const float*)d_in[1];
        Wr = (const float*)d_in[2]; Wi = (const float*)d_in[3];
        wgt = (const float*)d_in[4];
        long c0 = in_sizes[0], c1 = in_sizes[1];
        long c2 = in_sizes[2], c3 = in_sizes[3];
        cU = (c0 < c1) ? c0 : c1;
        cW = (c2 < c3) ? c2 : c3;
        cWg = in_sizes[4];
        nmu = REF_NMU; nfeat = REF_NFEAT; nsite = REF_NSITE;
    }

    dim3 block(128);
    dim3 grid((unsigned)((nsite + 127) / 128));
    switch (nmu) {
    case 1: lge_generic<1><<<grid, block>>>(Ur,Ui,Wr,Wi,wgt,out,(int)nsite,nfeat,cW,cU,cWg,o_cap); break;
    case 2: lge_generic<2><<<grid, block>>>(Ur,Ui,Wr,Wi,wgt,out,(int)nsite,nfeat,cW,cU,cWg,o_cap); break;
    case 3: lge_generic<3><<<grid, block>>>(Ur,Ui,Wr,Wi,wgt,out,(int)nsite,nfeat,cW,cU,cWg,o_cap); break;
    default: lge_generic<4><<<grid, block>>>(Ur,Ui,Wr,Wi,wgt,out,(int)nsite,nfeat,cW,cU,cWg,o_cap); break;
    }
}